// round 2
// baseline (speedup 1.0000x reference)
#include <cuda_runtime.h>

namespace {

constexpr int T = 2048;
constexpr int B = 4096;

typedef unsigned long long u64;

__device__ __forceinline__ u64 pack2(float lo, float hi) {
    u64 r; asm("mov.b64 %0,{%1,%2};" : "=l"(r) : "f"(lo), "f"(hi)); return r;
}
__device__ __forceinline__ void unpack2(u64 v, float& lo, float& hi) {
    asm("mov.b64 {%0,%1},%2;" : "=f"(lo), "=f"(hi) : "l"(v));
}
__device__ __forceinline__ u64 ffma2(u64 a, u64 b, u64 c) {
    u64 d; asm("fma.rn.f32x2 %0,%1,%2,%3;" : "=l"(d) : "l"(a), "l"(b), "l"(c)); return d;
}
__device__ __forceinline__ u64 fmul2(u64 a, u64 b) {
    u64 d; asm("mul.rn.f32x2 %0,%1,%2;" : "=l"(d) : "l"(a), "l"(b)); return d;
}
__device__ __forceinline__ u64 fadd2(u64 a, u64 b) {
    u64 d; asm("add.rn.f32x2 %0,%1,%2;" : "=l"(d) : "l"(a), "l"(b)); return d;
}
__device__ __forceinline__ float ex2a(float x) {
    float y; asm("ex2.approx.f32 %0,%1;" : "=f"(y) : "f"(x)); return y;
}
__device__ __forceinline__ float rcpa(float x) {
    float y; asm("rcp.approx.f32 %0,%1;" : "=f"(y) : "f"(x)); return y;
}
// sigmoid(x) = 1 / (1 + 2^(-x*log2(e)))   (~1e-6 accurate, inf-safe)
__device__ __forceinline__ float sigm(float x) {
    return rcpa(1.0f + ex2a(-1.4426950408889634f * x));
}
// tanh(v) = 2/(1 + 2^(-2v*log2(e))) - 1   (~1e-6 accurate, inf-safe)
__device__ __forceinline__ float tanhx(float v) {
    float e = ex2a(-2.8853900817779268f * v);
    return fmaf(2.0f, rcpa(1.0f + e), -1.0f);
}

// 4 threads per batch chain. Thread q in {0..3} owns hidden units {q, q+4},
// i.e. gate rows {q,q+4} (r), {8+q,12+q} (z), {16+q,20+q} (n).
// All weights register-resident as f32x2 pairs; inner loop is pure
// FFMA2 + 8 SHFL + MUFU, no shared/const loads.
__global__ void __launch_bounds__(64, 1) gru_fused_kernel(
    const float* __restrict__ x,
    const float* __restrict__ W_ih,
    const float* __restrict__ W_hh,
    const float* __restrict__ b_ih,
    const float* __restrict__ b_hh,
    const float* __restrict__ W_fc,
    const float* __restrict__ b_fc,
    float* __restrict__ out)
{
    const int tid = blockIdx.x * 64 + threadIdx.x;
    const int b = tid >> 2;
    const int q = tid & 3;

    // ---- pack weights into registers (one-time) ----
    u64 Wr[8], Wz[8], Wn[8];
#pragma unroll
    for (int k = 0; k < 8; k++) {
        Wr[k] = pack2(W_hh[(q     ) * 8 + k], W_hh[(q +  4) * 8 + k]);
        Wz[k] = pack2(W_hh[(q +  8) * 8 + k], W_hh[(q + 12) * 8 + k]);
        Wn[k] = pack2(W_hh[(q + 16) * 8 + k], W_hh[(q + 20) * 8 + k]);
    }
    u64 Ur[4], Uz[4], Un[4];
#pragma unroll
    for (int i = 0; i < 4; i++) {
        Ur[i] = pack2(W_ih[(q     ) * 4 + i], W_ih[(q +  4) * 4 + i]);
        Uz[i] = pack2(W_ih[(q +  8) * 4 + i], W_ih[(q + 12) * 4 + i]);
        Un[i] = pack2(W_ih[(q + 16) * 4 + i], W_ih[(q + 20) * 4 + i]);
    }
    const u64 br  = pack2(b_ih[q     ] + b_hh[q     ], b_ih[q +  4] + b_hh[q +  4]);
    const u64 bz  = pack2(b_ih[q +  8] + b_hh[q +  8], b_ih[q + 12] + b_hh[q + 12]);
    const u64 bxn = pack2(b_ih[q + 16], b_ih[q + 20]);
    const u64 bhn = pack2(b_hh[q + 16], b_hh[q + 20]);
    u64 Wf[4];
#pragma unroll
    for (int k = 0; k < 4; k++)
        Wf[k] = pack2(W_fc[q * 8 + k], W_fc[q * 8 + k + 4]);
    const float bf = b_fc[q];

    const float4* xp = reinterpret_cast<const float4*>(x) + (size_t)b * T;
    float* op = out + (size_t)b * T * 4 + q;

    u64 h2 = 0;                       // (h_q, h_{q+4}) = 0
    u64 p0 = 0, p1 = 0, p2 = 0, p3 = 0; // broadcast h pairs of the group
    float4 xv = xp[0];

#pragma unroll 2
    for (int t = 0; t < T; t++) {
        // prefetch next x (group-shared 128B line: 1 line serves 4 thr x 8 steps)
        float4 xnx = xp[(t + 1 < T) ? (t + 1) : t];

        // ---- emit y_{t-1} = b_fc[q] + sum_k W_fc[q,k] * h_{t-1,k} ----
        // p_j = (h_j, h_{j+4}); Wf[j] = (Wfc[q,j], Wfc[q,j+4]).
        // At t==0 this writes a dummy to slot 0, overwritten at t==1.
        {
            u64 ya = ffma2(Wf[0], p0, ffma2(Wf[2], p2, pack2(bf, 0.0f)));
            u64 yb = ffma2(Wf[1], p1, fmul2(Wf[3], p3));
            float yl, yh; unpack2(fadd2(ya, yb), yl, yh);
            int tp = t - (t > 0);
            op[tp * 4] = yl + yh;
        }

        // ---- splats of h_{t-1} ----
        float a0, a1, a2, a3, a4, a5, a6, a7;
        unpack2(p0, a0, a4); unpack2(p1, a1, a5);
        unpack2(p2, a2, a6); unpack2(p3, a3, a7);
        u64 s0 = pack2(a0, a0), s1 = pack2(a1, a1), s2 = pack2(a2, a2), s3 = pack2(a3, a3);
        u64 s4 = pack2(a4, a4), s5 = pack2(a5, a5), s6 = pack2(a6, a6), s7 = pack2(a7, a7);
        u64 sx0 = pack2(xv.x, xv.x), sx1 = pack2(xv.y, xv.y);
        u64 sx2 = pack2(xv.z, xv.z), sx3 = pack2(xv.w, xv.w);

        // ---- r gate pre-activation (two partial chains) ----
        u64 r0 = ffma2(Ur[0], sx0, br);
        u64 r1 = ffma2(Ur[1], sx1, fmul2(Ur[2], sx2));
        r0 = ffma2(Ur[3], sx3, r0);
        r0 = ffma2(Wr[0], s0, r0);  r1 = ffma2(Wr[1], s1, r1);
        r0 = ffma2(Wr[2], s2, r0);  r1 = ffma2(Wr[3], s3, r1);
        r0 = ffma2(Wr[4], s4, r0);  r1 = ffma2(Wr[5], s5, r1);
        r0 = ffma2(Wr[6], s6, r0);  r1 = ffma2(Wr[7], s7, r1);
        u64 ar = fadd2(r0, r1);

        // ---- z gate pre-activation ----
        u64 z0 = ffma2(Uz[0], sx0, bz);
        u64 z1 = ffma2(Uz[1], sx1, fmul2(Uz[2], sx2));
        z0 = ffma2(Uz[3], sx3, z0);
        z0 = ffma2(Wz[0], s0, z0);  z1 = ffma2(Wz[1], s1, z1);
        z0 = ffma2(Wz[2], s2, z0);  z1 = ffma2(Wz[3], s3, z1);
        z0 = ffma2(Wz[4], s4, z0);  z1 = ffma2(Wz[5], s5, z1);
        z0 = ffma2(Wz[6], s6, z0);  z1 = ffma2(Wz[7], s7, z1);
        u64 az = fadd2(z0, z1);

        // ---- hn = W_hh_n h + b_hh_n ----
        u64 n0 = ffma2(Wn[0], s0, bhn);
        u64 n1 = ffma2(Wn[1], s1, fmul2(Wn[2], s2));
        n0 = ffma2(Wn[3], s3, n0);
        n0 = ffma2(Wn[4], s4, n0);  n1 = ffma2(Wn[5], s5, n1);
        n0 = ffma2(Wn[6], s6, n0);  n1 = ffma2(Wn[7], s7, n1);
        u64 ahn = fadd2(n0, n1);

        // ---- xn = W_ih_n x + b_ih_n ----
        u64 e0 = ffma2(Un[0], sx0, bxn);
        u64 e1 = ffma2(Un[1], sx1, fmul2(Un[2], sx2));
        e0 = ffma2(Un[3], sx3, e0);
        u64 axn = fadd2(e0, e1);

        // ---- activations ----
        float rl, rh, zl, zh;
        unpack2(ar, rl, rh); unpack2(az, zl, zh);
        u64 r2 = pack2(sigm(rl), sigm(rh));
        u64 z2 = pack2(sigm(zl), sigm(zh));
        u64 v2 = ffma2(r2, ahn, axn);
        float vl, vh; unpack2(v2, vl, vh);
        u64 n2 = pack2(tanhx(vl), tanhx(vh));

        // ---- h = n + z*(h - n)  (negate n via sign-bit XOR) ----
        u64 d2 = fadd2(h2, n2 ^ 0x8000000080000000ULL);
        h2 = ffma2(z2, d2, n2);

        // ---- broadcast h_t within the 4-lane group (latency overlaps next iter) ----
        double hd = __longlong_as_double((long long)h2);
        p0 = (u64)__double_as_longlong(__shfl_sync(0xffffffffu, hd, 0, 4));
        p1 = (u64)__double_as_longlong(__shfl_sync(0xffffffffu, hd, 1, 4));
        p2 = (u64)__double_as_longlong(__shfl_sync(0xffffffffu, hd, 2, 4));
        p3 = (u64)__double_as_longlong(__shfl_sync(0xffffffffu, hd, 3, 4));

        xv = xnx;
    }

    // ---- final y_{T-1} ----
    {
        u64 ya = ffma2(Wf[0], p0, ffma2(Wf[2], p2, pack2(bf, 0.0f)));
        u64 yb = ffma2(Wf[1], p1, fmul2(Wf[3], p3));
        float yl, yh; unpack2(fadd2(ya, yb), yl, yh);
        op[(T - 1) * 4] = yl + yh;
    }
}

} // namespace

extern "C" void kernel_launch(void* const* d_in, const int* in_sizes, int n_in,
                              void* d_out, int out_size)
{
    const float* x    = (const float*)d_in[0];
    const float* W_ih = (const float*)d_in[1];
    const float* W_hh = (const float*)d_in[2];
    const float* b_ih = (const float*)d_in[3];
    const float* b_hh = (const float*)d_in[4];
    const float* W_fc = (const float*)d_in[5];
    const float* b_fc = (const float*)d_in[6];
    float* out = (float*)d_out;

    // 4096 batches * 4 threads = 16384 threads; 64-thread blocks -> 256 blocks
    gru_fused_kernel<<<(B * 4) / 64, 64>>>(x, W_ih, W_hh, b_ih, b_hh, W_fc, b_fc, out);
}